// round 8
// baseline (speedup 1.0000x reference)
#include <cuda_runtime.h>

#define NPTS   300000
#define NPAIRS 100000
#define KOFF   27
#define CIN    32
#define COUT   64
#define NGRP   8

// ---- scratch (no allocations allowed) ----
__device__ float g_sum[NGRP];
__device__ float g_sq[NGRP];
__device__ float g_mean[NGRP];
__device__ float g_inv[NGRP];
__device__ int   g_is64;

// ---- packed fp32x2 helpers (sm_100+) ----
__device__ __forceinline__ unsigned long long pack2(float lo, float hi) {
    unsigned long long r;
    asm("mov.b64 %0, {%1, %2};" : "=l"(r) : "f"(lo), "f"(hi));
    return r;
}
__device__ __forceinline__ float hadd2(unsigned long long v) {
    float lo, hi;
    asm("mov.b64 {%0, %1}, %2;" : "=f"(lo), "=f"(hi) : "l"(v));
    return lo + hi;
}
#define FMA2(acc, b, w) \
    asm("fma.rn.f32x2 %0, %1, %2, %0;" : "+l"(acc) : "l"(b), "l"(w))

__device__ __forceinline__ void red_add_v4(float* addr, float x, float y, float z, float w) {
    asm volatile("red.global.add.v4.f32 [%0], {%1, %2, %3, %4};"
                 :: "l"(addr), "f"(x), "f"(y), "f"(z), "f"(w) : "memory");
}

// Detect whether index arrays are int64 or int32 (jax x64 flag ambiguity).
__global__ void detect_kernel(const unsigned int* __restrict__ idx32) {
    __shared__ int s_any;
    if (threadIdx.x == 0) s_any = 0;
    __syncthreads();
    unsigned int v = 0;
    for (int i = threadIdx.x; i < 2048; i += blockDim.x)
        v |= idx32[2 * i + 1];
    if (v) atomicOr(&s_any, 1);
    __syncthreads();
    if (threadIdx.x == 0) g_is64 = (s_any == 0) ? 1 : 0;
}

__global__ void zero_kernel(float4* __restrict__ out, int n4) {
    int i = blockIdx.x * blockDim.x + threadIdx.x;
    if (i < n4) out[i] = make_float4(0.f, 0.f, 0.f, 0.f);
    if (blockIdx.x == 0 && threadIdx.x < NGRP) {
        g_sum[threadIdx.x] = 0.f;
        g_sq[threadIdx.x]  = 0.f;
    }
}

__device__ __forceinline__ int load_idx(const void* p, long long pos, int is64) {
    if (is64) return (int)((const long long*)p)[pos];
    return ((const int*)p)[pos];
}

// Sparse conv: one warp per batch of 32 pairs.
// LOAD PHASE (once per warp): 8 coalesced LDG.128 staging all 32 feature
// rows (4 KB) into smem.
// COMPUTE PHASE: per pair, 8 broadcast LDS.128 feed fma.rn.f32x2 pairs
// (lane owns channels 2l, 2l+1). Lane pair (2m, 2m+1) exchanges results
// via 2x shfl.xor(1); the even lane issues ONE red.global.add.v4.f32
// covering channels 4m..4m+3 -> 16 RED lane-ops per pair instead of 32.
__global__ __launch_bounds__(256, 2)
void conv_kernel(const float* __restrict__ feats,
                 const float* __restrict__ weight,
                 const void*  __restrict__ in_idx,
                 const void*  __restrict__ out_idx,
                 float*       __restrict__ out) {
    const int k    = blockIdx.y;
    const int lane = threadIdx.x & 31;
    const int warp = threadIdx.x >> 5;

    __shared__ float      ws[CIN * COUT];
    __shared__ ulonglong2 stage[8][32 * 8];   // 8 warps x (32 rows x 8 chunks of 16B)

    const float* wk = weight + (long long)k * CIN * COUT;
    for (int i = threadIdx.x; i < CIN * COUT; i += blockDim.x) ws[i] = wk[i];
    __syncthreads();

    // wp0[c2] = (W[2c2][2l], W[2c2+1][2l]) ; wp1 same for channel 2l+1
    unsigned long long wp0[16], wp1[16];
#pragma unroll
    for (int c2 = 0; c2 < 16; c2++) {
        wp0[c2] = pack2(ws[(2*c2) * COUT + 2*lane],     ws[(2*c2+1) * COUT + 2*lane]);
        wp1[c2] = pack2(ws[(2*c2) * COUT + 2*lane + 1], ws[(2*c2+1) * COUT + 2*lane + 1]);
    }

    const int is64 = g_is64;
    const long long base = (long long)k * NPAIRS;
    const int p0 = (blockIdx.x * 8 + warp) * 32;
    if (p0 >= NPAIRS) return;           // NPAIRS % 32 == 0: active warps are full

    const int p = p0 + lane;
    int ir   = load_idx(in_idx,  base + p, is64);
    int orow = load_idx(out_idx, base + p, is64);

    // ---- load phase: 8 LDG.128, 4 rows each ----
    ulonglong2* st = stage[warp];
    const int sub = lane >> 3;          // which of 4 rows in this group
    const int q   = lane & 7;           // 16B chunk within row
#pragma unroll
    for (int g = 0; g < 8; g++) {
        const int r    = 4 * g + sub;
        const int irow = __shfl_sync(0xffffffffu, ir, r);
        ulonglong2 v = __ldg((const ulonglong2*)(feats + (long long)irow * CIN) + q);
        st[r * 8 + q] = v;
    }
    __syncwarp();

    const bool is_even = !(lane & 1);
    const int  ch4     = (lane >> 1) * 4;   // even lane's v4 channel base

    // ---- compute phase ----
    for (int j = 0; j < 32; j++) {
        const int ro = __shfl_sync(0xffffffffu, orow, j);
        const ulonglong2* rowp = st + j * 8;
        unsigned long long a0 = 0ull, a1 = 0ull;
#pragma unroll
        for (int c = 0; c < 8; c++) {
            ulonglong2 fv = rowp[c];    // broadcast LDS.128
            FMA2(a0, fv.x, wp0[2*c]);   FMA2(a1, fv.x, wp1[2*c]);
            FMA2(a0, fv.y, wp0[2*c+1]); FMA2(a1, fv.y, wp1[2*c+1]);
        }
        float v0 = hadd2(a0);                       // channel 2*lane
        float v1 = hadd2(a1);                       // channel 2*lane+1
        float o0 = __shfl_xor_sync(0xffffffffu, v0, 1);
        float o1 = __shfl_xor_sync(0xffffffffu, v1, 1);
        if (is_even)
            red_add_v4(out + (long long)ro * COUT + ch4, v0, v1, o0, o1);
    }
}

// GroupNorm stats: float4 loads; 4 channels per thread all lie in one group.
__global__ void stats_kernel(const float4* __restrict__ out) {
    const int c4   = threadIdx.x & 15;
    const int ty   = threadIdx.x >> 4;
    const int lane = threadIdx.x & 31;
    __shared__ float s_sum[NGRP], s_sq[NGRP];
    if (threadIdx.x < NGRP) { s_sum[threadIdx.x] = 0.f; s_sq[threadIdx.x] = 0.f; }
    __syncthreads();

    float sum = 0.f, sq = 0.f;
#pragma unroll 4
    for (int row = blockIdx.x * 16 + ty; row < NPTS; row += gridDim.x * 16) {
        float4 v = __ldg(out + row * 16 + c4);
        sum += (v.x + v.y) + (v.z + v.w);
        sq   = fmaf(v.x, v.x, fmaf(v.y, v.y, fmaf(v.z, v.z, fmaf(v.w, v.w, sq))));
    }
    sum += __shfl_xor_sync(0xffffffffu, sum, 16);
    sq  += __shfl_xor_sync(0xffffffffu, sq,  16);
    sum += __shfl_xor_sync(0xffffffffu, sum, 1);
    sq  += __shfl_xor_sync(0xffffffffu, sq,  1);
    if (lane < 16 && !(lane & 1)) {
        atomicAdd(&s_sum[lane >> 1], sum);
        atomicAdd(&s_sq[lane >> 1],  sq);
    }
    __syncthreads();
    if (threadIdx.x < NGRP) {
        atomicAdd(&g_sum[threadIdx.x], s_sum[threadIdx.x]);
        atomicAdd(&g_sq[threadIdx.x],  s_sq[threadIdx.x]);
    }
}

__global__ void finalize_kernel() {
    int g = threadIdx.x;
    if (g < NGRP) {
        const float cnt = (float)NPTS * (COUT / NGRP);
        float m   = g_sum[g] / cnt;
        float var = g_sq[g] / cnt - m * m;
        g_mean[g] = m;
        g_inv[g]  = rsqrtf(var + 1e-5f);
    }
}

// Fused affine + LeakyReLU, float4 in/out.
__global__ void norm_kernel(float4* __restrict__ out,
                            const float4* __restrict__ gamma4,
                            const float4* __restrict__ beta4) {
    const int c4 = threadIdx.x & 15;
    const int ty = threadIdx.x >> 4;
    const int g  = c4 >> 1;
    const float m   = g_mean[g];
    const float inv = g_inv[g];
    float4 ga = __ldg(gamma4 + c4);
    float4 be = __ldg(beta4  + c4);
    ga.x *= inv; ga.y *= inv; ga.z *= inv; ga.w *= inv;
    be.x -= m * ga.x; be.y -= m * ga.y; be.z -= m * ga.z; be.w -= m * ga.w;
#pragma unroll 4
    for (int row = blockIdx.x * 16 + ty; row < NPTS; row += gridDim.x * 16) {
        float4 v = out[row * 16 + c4];
        v.x = fmaf(v.x, ga.x, be.x); v.x = (v.x >= 0.f) ? v.x : 0.01f * v.x;
        v.y = fmaf(v.y, ga.y, be.y); v.y = (v.y >= 0.f) ? v.y : 0.01f * v.y;
        v.z = fmaf(v.z, ga.z, be.z); v.z = (v.z >= 0.f) ? v.z : 0.01f * v.z;
        v.w = fmaf(v.w, ga.w, be.w); v.w = (v.w >= 0.f) ? v.w : 0.01f * v.w;
        out[row * 16 + c4] = v;
    }
}

extern "C" void kernel_launch(void* const* d_in, const int* in_sizes, int n_in,
                              void* d_out, int out_size) {
    const float* feats   = (const float*)d_in[0];
    const float* weight  = (const float*)d_in[1];
    const float* gamma   = (const float*)d_in[2];
    const float* beta    = (const float*)d_in[3];
    const void*  in_idx  = d_in[4];
    const void*  out_idx = d_in[5];
    float* out = (float*)d_out;

    detect_kernel<<<1, 256>>>((const unsigned int*)in_idx);

    const int n4 = NPTS * COUT / 4;
    zero_kernel<<<(n4 + 255) / 256, 256>>>((float4*)out, n4);

    dim3 cgrid((NPAIRS + 255) / 256, KOFF);   // 391 x 27 blocks, 8 warps each
    conv_kernel<<<cgrid, 256>>>(feats, weight, in_idx, out_idx, out);

    stats_kernel<<<1184, 256>>>((const float4*)out);
    finalize_kernel<<<1, 32>>>();
    norm_kernel<<<2048, 256>>>((float4*)out, (const float4*)gamma, (const float4*)beta);
}

// round 9
// speedup vs baseline: 1.0578x; 1.0578x over previous
#include <cuda_runtime.h>

#define NPTS   300000
#define NPAIRS 100000
#define KOFF   27
#define CIN    32
#define COUT   64
#define NGRP   8

// ---- scratch (no allocations allowed) ----
__device__ float g_sum[NGRP];
__device__ float g_sq[NGRP];
__device__ float g_mean[NGRP];
__device__ float g_inv[NGRP];
__device__ int   g_is64;

// ---- packed fp32x2 helpers (sm_100+) ----
__device__ __forceinline__ unsigned long long pack2(float lo, float hi) {
    unsigned long long r;
    asm("mov.b64 %0, {%1, %2};" : "=l"(r) : "f"(lo), "f"(hi));
    return r;
}
__device__ __forceinline__ float hadd2(unsigned long long v) {
    float lo, hi;
    asm("mov.b64 {%0, %1}, %2;" : "=f"(lo), "=f"(hi) : "l"(v));
    return lo + hi;
}
#define FMA2(acc, b, w) \
    asm("fma.rn.f32x2 %0, %1, %2, %0;" : "+l"(acc) : "l"(b), "l"(w))

__device__ __forceinline__ void red_add_v2(float* addr, float x, float y) {
    asm volatile("red.global.add.v2.f32 [%0], {%1, %2};"
                 :: "l"(addr), "f"(x), "f"(y) : "memory");
}

// zero output + scratch; block 0 also detects int64-vs-int32 indices
// (jax x64 ambiguity: if int64, high words of first 4K entries are all 0).
__global__ void zero_kernel(float4* __restrict__ out, int n4,
                            const unsigned int* __restrict__ idx32) {
    int i = blockIdx.x * blockDim.x + threadIdx.x;
    if (i < n4) out[i] = make_float4(0.f, 0.f, 0.f, 0.f);
    if (blockIdx.x == 0) {
        __shared__ int s_any;
        if (threadIdx.x == 0) s_any = 0;
        __syncthreads();
        unsigned int v = 0;
        for (int t = threadIdx.x; t < 2048; t += blockDim.x)
            v |= idx32[2 * t + 1];
        if (v) atomicOr(&s_any, 1);
        __syncthreads();
        if (threadIdx.x == 0) g_is64 = (s_any == 0) ? 1 : 0;
        if (threadIdx.x < NGRP) { g_sum[threadIdx.x] = 0.f; g_sq[threadIdx.x] = 0.f; }
    }
}

__device__ __forceinline__ int load_idx(const void* p, long long pos, int is64) {
    if (is64) return (int)((const long long*)p)[pos];
    return ((const int*)p)[pos];
}

// Sparse conv: one warp per batch of 32 pairs.
// LOAD PHASE: 8 coalesced LDG.128 staging all 32 feature rows (4 KB) into smem.
// COMPUTE PHASE: 2 records per iteration — four independent f32x2 FMA chains
// (a0,a1,b0,b1) so shfl/LDS of one record hides under the other's FMA tail.
// Scatter: red.global.add.v2.f32 from all 32 lanes (proven best config).
__global__ __launch_bounds__(256, 2)
void conv_kernel(const float* __restrict__ feats,
                 const float* __restrict__ weight,
                 const void*  __restrict__ in_idx,
                 const void*  __restrict__ out_idx,
                 float*       __restrict__ out) {
    const int k    = blockIdx.y;
    const int lane = threadIdx.x & 31;
    const int warp = threadIdx.x >> 5;

    __shared__ float      ws[CIN * COUT];
    __shared__ ulonglong2 stage[8][32 * 8];   // 8 warps x (32 rows x 8 chunks of 16B)

    const float* wk = weight + (long long)k * CIN * COUT;
    for (int i = threadIdx.x; i < CIN * COUT; i += blockDim.x) ws[i] = wk[i];
    __syncthreads();

    // wp0[c2] = (W[2c2][2l], W[2c2+1][2l]) ; wp1 same for channel 2l+1
    unsigned long long wp0[16], wp1[16];
#pragma unroll
    for (int c2 = 0; c2 < 16; c2++) {
        wp0[c2] = pack2(ws[(2*c2) * COUT + 2*lane],     ws[(2*c2+1) * COUT + 2*lane]);
        wp1[c2] = pack2(ws[(2*c2) * COUT + 2*lane + 1], ws[(2*c2+1) * COUT + 2*lane + 1]);
    }

    const int is64 = g_is64;
    const long long base = (long long)k * NPAIRS;
    const int p0 = (blockIdx.x * 8 + warp) * 32;
    if (p0 >= NPAIRS) return;           // NPAIRS % 32 == 0: active warps are full

    const int p = p0 + lane;
    int ir   = load_idx(in_idx,  base + p, is64);
    int orow = load_idx(out_idx, base + p, is64);

    // ---- load phase: 8 LDG.128, 4 rows each ----
    ulonglong2* st = stage[warp];
    const int sub = lane >> 3;          // which of 4 rows in this group
    const int q   = lane & 7;           // 16B chunk within row
#pragma unroll
    for (int g = 0; g < 8; g++) {
        const int r    = 4 * g + sub;
        const int irow = __shfl_sync(0xffffffffu, ir, r);
        ulonglong2 v = __ldg((const ulonglong2*)(feats + (long long)irow * CIN) + q);
        st[r * 8 + q] = v;
    }
    __syncwarp();

    // ---- compute phase: 2 records per iteration ----
    for (int j = 0; j < 32; j += 2) {
        const int ro0 = __shfl_sync(0xffffffffu, orow, j);
        const int ro1 = __shfl_sync(0xffffffffu, orow, j + 1);
        const ulonglong2* r0 = st + j * 8;
        const ulonglong2* r1 = r0 + 8;
        unsigned long long a0 = 0ull, a1 = 0ull, b0 = 0ull, b1 = 0ull;
#pragma unroll
        for (int c = 0; c < 8; c++) {
            ulonglong2 f0 = r0[c];      // broadcast LDS.128
            ulonglong2 f1 = r1[c];
            FMA2(a0, f0.x, wp0[2*c]);   FMA2(a1, f0.x, wp1[2*c]);
            FMA2(b0, f1.x, wp0[2*c]);   FMA2(b1, f1.x, wp1[2*c]);
            FMA2(a0, f0.y, wp0[2*c+1]); FMA2(a1, f0.y, wp1[2*c+1]);
            FMA2(b0, f1.y, wp0[2*c+1]); FMA2(b1, f1.y, wp1[2*c+1]);
        }
        red_add_v2(out + (long long)ro0 * COUT + 2*lane, hadd2(a0), hadd2(a1));
        red_add_v2(out + (long long)ro1 * COUT + 2*lane, hadd2(b0), hadd2(b1));
    }
}

// GroupNorm stats: 2 float4 rows per thread per iteration (double MLP).
__global__ void stats_kernel(const float4* __restrict__ out) {
    const int c4   = threadIdx.x & 15;
    const int ty   = threadIdx.x >> 4;
    const int lane = threadIdx.x & 31;
    __shared__ float s_sum[NGRP], s_sq[NGRP];
    if (threadIdx.x < NGRP) { s_sum[threadIdx.x] = 0.f; s_sq[threadIdx.x] = 0.f; }
    __syncthreads();

    float sum = 0.f, sq = 0.f;
    for (int row = blockIdx.x * 32 + ty; row < NPTS; row += gridDim.x * 32) {
        float4 v = __ldg(out + row * 16 + c4);
        int row2 = row + 16;
        if (row2 < NPTS) {
            float4 u = __ldg(out + row2 * 16 + c4);
            sum += (u.x + u.y) + (u.z + u.w);
            sq   = fmaf(u.x, u.x, fmaf(u.y, u.y, fmaf(u.z, u.z, fmaf(u.w, u.w, sq))));
        }
        sum += (v.x + v.y) + (v.z + v.w);
        sq   = fmaf(v.x, v.x, fmaf(v.y, v.y, fmaf(v.z, v.z, fmaf(v.w, v.w, sq))));
    }
    // lanes {2g, 2g+1, 2g+16, 2g+17} share group g
    sum += __shfl_xor_sync(0xffffffffu, sum, 16);
    sq  += __shfl_xor_sync(0xffffffffu, sq,  16);
    sum += __shfl_xor_sync(0xffffffffu, sum, 1);
    sq  += __shfl_xor_sync(0xffffffffu, sq,  1);
    if (lane < 16 && !(lane & 1)) {
        atomicAdd(&s_sum[lane >> 1], sum);
        atomicAdd(&s_sq[lane >> 1],  sq);
    }
    __syncthreads();
    if (threadIdx.x < NGRP) {
        atomicAdd(&g_sum[threadIdx.x], s_sum[threadIdx.x]);
        atomicAdd(&g_sq[threadIdx.x],  s_sq[threadIdx.x]);
    }
}

__global__ void finalize_kernel() {
    int g = threadIdx.x;
    if (g < NGRP) {
        const float cnt = (float)NPTS * (COUT / NGRP);
        float m   = g_sum[g] / cnt;
        float var = g_sq[g] / cnt - m * m;
        g_mean[g] = m;
        g_inv[g]  = rsqrtf(var + 1e-5f);
    }
}

__device__ __forceinline__ float4 aff_lrelu(float4 v, float4 ga, float4 be) {
    v.x = fmaf(v.x, ga.x, be.x); v.x = (v.x >= 0.f) ? v.x : 0.01f * v.x;
    v.y = fmaf(v.y, ga.y, be.y); v.y = (v.y >= 0.f) ? v.y : 0.01f * v.y;
    v.z = fmaf(v.z, ga.z, be.z); v.z = (v.z >= 0.f) ? v.z : 0.01f * v.z;
    v.w = fmaf(v.w, ga.w, be.w); v.w = (v.w >= 0.f) ? v.w : 0.01f * v.w;
    return v;
}

// Fused affine + LeakyReLU: 2 float4 rows per thread per iteration.
__global__ void norm_kernel(float4* __restrict__ out,
                            const float4* __restrict__ gamma4,
                            const float4* __restrict__ beta4) {
    const int c4 = threadIdx.x & 15;
    const int ty = threadIdx.x >> 4;
    const int g  = c4 >> 1;
    const float m   = g_mean[g];
    const float inv = g_inv[g];
    float4 ga = __ldg(gamma4 + c4);
    float4 be = __ldg(beta4  + c4);
    ga.x *= inv; ga.y *= inv; ga.z *= inv; ga.w *= inv;
    be.x -= m * ga.x; be.y -= m * ga.y; be.z -= m * ga.z; be.w -= m * ga.w;
    for (int row = blockIdx.x * 32 + ty; row < NPTS; row += gridDim.x * 32) {
        float4 v = out[row * 16 + c4];
        int row2 = row + 16;
        float4 u;
        bool has2 = (row2 < NPTS);
        if (has2) u = out[row2 * 16 + c4];
        out[row * 16 + c4] = aff_lrelu(v, ga, be);
        if (has2) out[row2 * 16 + c4] = aff_lrelu(u, ga, be);
    }
}

extern "C" void kernel_launch(void* const* d_in, const int* in_sizes, int n_in,
                              void* d_out, int out_size) {
    const float* feats   = (const float*)d_in[0];
    const float* weight  = (const float*)d_in[1];
    const float* gamma   = (const float*)d_in[2];
    const float* beta    = (const float*)d_in[3];
    const void*  in_idx  = d_in[4];
    const void*  out_idx = d_in[5];
    float* out = (float*)d_out;

    const int n4 = NPTS * COUT / 4;
    zero_kernel<<<(n4 + 255) / 256, 256>>>((float4*)out, n4,
                                           (const unsigned int*)in_idx);

    dim3 cgrid((NPAIRS + 255) / 256, KOFF);   // 391 x 27 blocks, 8 warps each
    conv_kernel<<<cgrid, 256>>>(feats, weight, in_idx, out_idx, out);

    stats_kernel<<<1184, 256>>>((const float4*)out);
    finalize_kernel<<<1, 32>>>();
    norm_kernel<<<1184, 256>>>((float4*)out, (const float4*)gamma, (const float4*)beta);
}

// round 10
// speedup vs baseline: 1.1045x; 1.0441x over previous
#include <cuda_runtime.h>

#define NPTS   300000
#define NPAIRS 100000
#define KOFF   27
#define CIN    32
#define COUT   64
#define NGRP   8

// ---- scratch (no allocations allowed) ----
__device__ float g_sum[NGRP];
__device__ float g_sq[NGRP];
__device__ int   g_is64;

// ---- packed fp32x2 helpers (sm_100+) ----
__device__ __forceinline__ unsigned long long pack2(float lo, float hi) {
    unsigned long long r;
    asm("mov.b64 %0, {%1, %2};" : "=l"(r) : "f"(lo), "f"(hi));
    return r;
}
__device__ __forceinline__ float hadd2(unsigned long long v) {
    float lo, hi;
    asm("mov.b64 {%0, %1}, %2;" : "=f"(lo), "=f"(hi) : "l"(v));
    return lo + hi;
}
#define FMA2(acc, b, w) \
    asm("fma.rn.f32x2 %0, %1, %2, %0;" : "+l"(acc) : "l"(b), "l"(w))

__device__ __forceinline__ void red_add_v2(float* addr, float x, float y) {
    asm volatile("red.global.add.v2.f32 [%0], {%1, %2};"
                 :: "l"(addr), "f"(x), "f"(y) : "memory");
}

// zero output + scratch; block 0 also detects int64-vs-int32 indices
// (jax x64 ambiguity: if int64, high words of first 4K entries are all 0).
__global__ void zero_kernel(float4* __restrict__ out, int n4,
                            const unsigned int* __restrict__ idx32) {
    int i = blockIdx.x * blockDim.x + threadIdx.x;
    if (i < n4) out[i] = make_float4(0.f, 0.f, 0.f, 0.f);
    if (blockIdx.x == 0) {
        __shared__ int s_any;
        if (threadIdx.x == 0) s_any = 0;
        __syncthreads();
        unsigned int v = 0;
        for (int t = threadIdx.x; t < 2048; t += blockDim.x)
            v |= idx32[2 * t + 1];
        if (v) atomicOr(&s_any, 1);
        __syncthreads();
        if (threadIdx.x == 0) g_is64 = (s_any == 0) ? 1 : 0;
        if (threadIdx.x < NGRP) { g_sum[threadIdx.x] = 0.f; g_sq[threadIdx.x] = 0.f; }
    }
}

__device__ __forceinline__ int load_idx(const void* p, long long pos, int is64) {
    if (is64) return (int)((const long long*)p)[pos];
    return ((const int*)p)[pos];
}

// Sparse conv: one warp per batch of 32 pairs; 128-thread blocks for higher
// resident-warp count (launch_bounds(128,5) -> up to 20 warps/SM).
// Weights packed straight from global into 64 regs/lane (one-time, L2-hot).
// LOAD PHASE: 8 coalesced LDG.128 staging 32 feature rows (4 KB) into smem.
// COMPUTE PHASE: 2 records/iter, four independent f32x2 FMA chains.
// Scatter: red.global.add.v2.f32 from all 32 lanes (measured-best config).
__global__ __launch_bounds__(128, 5)
void conv_kernel(const float* __restrict__ feats,
                 const float* __restrict__ weight,
                 const void*  __restrict__ in_idx,
                 const void*  __restrict__ out_idx,
                 float*       __restrict__ out) {
    const int k    = blockIdx.y;
    const int lane = threadIdx.x & 31;
    const int warp = threadIdx.x >> 5;

    __shared__ ulonglong2 stage[4][32 * 8];   // 4 warps x (32 rows x 8 chunks of 16B)

    const int p0 = (blockIdx.x * 4 + warp) * 32;
    if (p0 >= NPAIRS) return;           // NPAIRS % 32 == 0: active warps are full

    // Pack weights from global: wp0[c2] = (W[2c2][2l], W[2c2+1][2l]); wp1 for 2l+1.
    const float* wk = weight + (long long)k * CIN * COUT;
    unsigned long long wp0[16], wp1[16];
#pragma unroll
    for (int c2 = 0; c2 < 16; c2++) {
        wp0[c2] = pack2(__ldg(wk + (2*c2) * COUT + 2*lane),
                        __ldg(wk + (2*c2+1) * COUT + 2*lane));
        wp1[c2] = pack2(__ldg(wk + (2*c2) * COUT + 2*lane + 1),
                        __ldg(wk + (2*c2+1) * COUT + 2*lane + 1));
    }

    const int is64 = g_is64;
    const long long base = (long long)k * NPAIRS;
    const int p = p0 + lane;
    int ir   = load_idx(in_idx,  base + p, is64);
    int orow = load_idx(out_idx, base + p, is64);

    // ---- load phase: 8 LDG.128, 4 rows each ----
    ulonglong2* st = stage[warp];
    const int sub = lane >> 3;          // which of 4 rows in this group
    const int q   = lane & 7;           // 16B chunk within row
#pragma unroll
    for (int g = 0; g < 8; g++) {
        const int r    = 4 * g + sub;
        const int irow = __shfl_sync(0xffffffffu, ir, r);
        ulonglong2 v = __ldg((const ulonglong2*)(feats + (long long)irow * CIN) + q);
        st[r * 8 + q] = v;
    }
    __syncwarp();

    // ---- compute phase: 2 records per iteration ----
    for (int j = 0; j < 32; j += 2) {
        const int ro0 = __shfl_sync(0xffffffffu, orow, j);
        const int ro1 = __shfl_sync(0xffffffffu, orow, j + 1);
        const ulonglong2* r0 = st + j * 8;
        const ulonglong2* r1 = r0 + 8;
        unsigned long long a0 = 0ull, a1 = 0ull, b0 = 0ull, b1 = 0ull;
#pragma unroll
        for (int c = 0; c < 8; c++) {
            ulonglong2 f0 = r0[c];      // broadcast LDS.128
            ulonglong2 f1 = r1[c];
            FMA2(a0, f0.x, wp0[2*c]);   FMA2(a1, f0.x, wp1[2*c]);
            FMA2(b0, f1.x, wp0[2*c]);   FMA2(b1, f1.x, wp1[2*c]);
            FMA2(a0, f0.y, wp0[2*c+1]); FMA2(a1, f0.y, wp1[2*c+1]);
            FMA2(b0, f1.y, wp0[2*c+1]); FMA2(b1, f1.y, wp1[2*c+1]);
        }
        red_add_v2(out + (long long)ro0 * COUT + 2*lane, hadd2(a0), hadd2(a1));
        red_add_v2(out + (long long)ro1 * COUT + 2*lane, hadd2(b0), hadd2(b1));
    }
}

// GroupNorm stats: 2 float4 rows per thread per iteration (double MLP).
__global__ void stats_kernel(const float4* __restrict__ out) {
    const int c4   = threadIdx.x & 15;
    const int ty   = threadIdx.x >> 4;
    const int lane = threadIdx.x & 31;
    __shared__ float s_sum[NGRP], s_sq[NGRP];
    if (threadIdx.x < NGRP) { s_sum[threadIdx.x] = 0.f; s_sq[threadIdx.x] = 0.f; }
    __syncthreads();

    float sum = 0.f, sq = 0.f;
    for (int row = blockIdx.x * 32 + ty; row < NPTS; row += gridDim.x * 32) {
        float4 v = __ldg(out + row * 16 + c4);
        int row2 = row + 16;
        if (row2 < NPTS) {
            float4 u = __ldg(out + row2 * 16 + c4);
            sum += (u.x + u.y) + (u.z + u.w);
            sq   = fmaf(u.x, u.x, fmaf(u.y, u.y, fmaf(u.z, u.z, fmaf(u.w, u.w, sq))));
        }
        sum += (v.x + v.y) + (v.z + v.w);
        sq   = fmaf(v.x, v.x, fmaf(v.y, v.y, fmaf(v.z, v.z, fmaf(v.w, v.w, sq))));
    }
    // lanes {2g, 2g+1, 2g+16, 2g+17} share group g
    sum += __shfl_xor_sync(0xffffffffu, sum, 16);
    sq  += __shfl_xor_sync(0xffffffffu, sq,  16);
    sum += __shfl_xor_sync(0xffffffffu, sum, 1);
    sq  += __shfl_xor_sync(0xffffffffu, sq,  1);
    if (lane < 16 && !(lane & 1)) {
        atomicAdd(&s_sum[lane >> 1], sum);
        atomicAdd(&s_sq[lane >> 1],  sq);
    }
    __syncthreads();
    if (threadIdx.x < NGRP) {
        atomicAdd(&g_sum[threadIdx.x], s_sum[threadIdx.x]);
        atomicAdd(&g_sq[threadIdx.x],  s_sq[threadIdx.x]);
    }
}

__device__ __forceinline__ float4 aff_lrelu(float4 v, float4 ga, float4 be) {
    v.x = fmaf(v.x, ga.x, be.x); v.x = (v.x >= 0.f) ? v.x : 0.01f * v.x;
    v.y = fmaf(v.y, ga.y, be.y); v.y = (v.y >= 0.f) ? v.y : 0.01f * v.y;
    v.z = fmaf(v.z, ga.z, be.z); v.z = (v.z >= 0.f) ? v.z : 0.01f * v.z;
    v.w = fmaf(v.w, ga.w, be.w); v.w = (v.w >= 0.f) ? v.w : 0.01f * v.w;
    return v;
}

// Fused finalize + affine + LeakyReLU: mean/inv computed inline from the
// global accumulators (kernel boundary after stats_kernel is the sync).
__global__ void norm_kernel(float4* __restrict__ out,
                            const float4* __restrict__ gamma4,
                            const float4* __restrict__ beta4) {
    const int c4 = threadIdx.x & 15;
    const int ty = threadIdx.x >> 4;
    const int g  = c4 >> 1;
    const float cnt = (float)NPTS * (COUT / NGRP);
    const float m   = g_sum[g] / cnt;
    const float var = g_sq[g] / cnt - m * m;
    const float inv = rsqrtf(var + 1e-5f);
    float4 ga = __ldg(gamma4 + c4);
    float4 be = __ldg(beta4  + c4);
    ga.x *= inv; ga.y *= inv; ga.z *= inv; ga.w *= inv;
    be.x -= m * ga.x; be.y -= m * ga.y; be.z -= m * ga.z; be.w -= m * ga.w;
    for (int row = blockIdx.x * 32 + ty; row < NPTS; row += gridDim.x * 32) {
        float4 v = out[row * 16 + c4];
        int row2 = row + 16;
        float4 u;
        bool has2 = (row2 < NPTS);
        if (has2) u = out[row2 * 16 + c4];
        out[row * 16 + c4] = aff_lrelu(v, ga, be);
        if (has2) out[row2 * 16 + c4] = aff_lrelu(u, ga, be);
    }
}

extern "C" void kernel_launch(void* const* d_in, const int* in_sizes, int n_in,
                              void* d_out, int out_size) {
    const float* feats   = (const float*)d_in[0];
    const float* weight  = (const float*)d_in[1];
    const float* gamma   = (const float*)d_in[2];
    const float* beta    = (const float*)d_in[3];
    const void*  in_idx  = d_in[4];
    const void*  out_idx = d_in[5];
    float* out = (float*)d_out;

    const int n4 = NPTS * COUT / 4;
    zero_kernel<<<(n4 + 255) / 256, 256>>>((float4*)out, n4,
                                           (const unsigned int*)in_idx);

    dim3 cgrid((NPAIRS + 127) / 128, KOFF);   // 782 x 27 blocks, 4 warps each
    conv_kernel<<<cgrid, 128>>>(feats, weight, in_idx, out_idx, out);

    stats_kernel<<<1184, 256>>>((const float4*)out);
    norm_kernel<<<1184, 256>>>((float4*)out, (const float4*)gamma, (const float4*)beta);
}

// round 11
// speedup vs baseline: 1.1550x; 1.0458x over previous
#include <cuda_runtime.h>

#define NPTS   300000
#define NPAIRS 100000
#define KOFF   27
#define CIN    32
#define COUT   64
#define NGRP   8
#define NB     5            // batches (of 32 pairs) per warp
#define NBATCH 3125         // 32-pair batches per k-offset (100000/32)

// ---- scratch (no allocations allowed) ----
__device__ float g_sum[NGRP];
__device__ float g_sq[NGRP];
__device__ int   g_is64;

// ---- packed fp32x2 helpers (sm_100+) ----
__device__ __forceinline__ unsigned long long pack2(float lo, float hi) {
    unsigned long long r;
    asm("mov.b64 %0, {%1, %2};" : "=l"(r) : "f"(lo), "f"(hi));
    return r;
}
__device__ __forceinline__ float hadd2(unsigned long long v) {
    float lo, hi;
    asm("mov.b64 {%0, %1}, %2;" : "=f"(lo), "=f"(hi) : "l"(v));
    return lo + hi;
}
#define FMA2(acc, b, w) \
    asm("fma.rn.f32x2 %0, %1, %2, %0;" : "+l"(acc) : "l"(b), "l"(w))

__device__ __forceinline__ void red_add_v2(float* addr, float x, float y) {
    asm volatile("red.global.add.v2.f32 [%0], {%1, %2};"
                 :: "l"(addr), "f"(x), "f"(y) : "memory");
}

__device__ __forceinline__ void cp_async16(unsigned int saddr, const void* gptr) {
    asm volatile("cp.async.cg.shared.global [%0], [%1], 16;"
                 :: "r"(saddr), "l"(gptr) : "memory");
}
#define CP_COMMIT() asm volatile("cp.async.commit_group;" ::: "memory")
#define CP_WAIT1()  asm volatile("cp.async.wait_group 1;"  ::: "memory")

// zero output + scratch; block 0 also detects int64-vs-int32 indices
// (jax x64 ambiguity: if int64, high words of first 4K entries are all 0).
__global__ void zero_kernel(float4* __restrict__ out, int n4,
                            const unsigned int* __restrict__ idx32) {
    int i = blockIdx.x * blockDim.x + threadIdx.x;
    if (i < n4) out[i] = make_float4(0.f, 0.f, 0.f, 0.f);
    if (blockIdx.x == 0) {
        __shared__ int s_any;
        if (threadIdx.x == 0) s_any = 0;
        __syncthreads();
        unsigned int v = 0;
        for (int t = threadIdx.x; t < 2048; t += blockDim.x)
            v |= idx32[2 * t + 1];
        if (v) atomicOr(&s_any, 1);
        __syncthreads();
        if (threadIdx.x == 0) g_is64 = (s_any == 0) ? 1 : 0;
        if (threadIdx.x < NGRP) { g_sum[threadIdx.x] = 0.f; g_sq[threadIdx.x] = 0.f; }
    }
}

__device__ __forceinline__ int load_idx(const void* p, long long pos, int is64) {
    if (is64) return (int)((const long long*)p)[pos];
    return ((const int*)p)[pos];
}

// Sparse conv with a double-buffered cp.async pipeline.
// Each warp owns NB=5 consecutive 32-pair batches. While batch t computes,
// batch t+1's 32 feature rows (4 KB) stream global->smem via cp.async.cg;
// index loads are pipelined two batches ahead so cp.async addressing never
// stalls. Compute: 2 records/iter, four f32x2 FMA chains (lane owns channels
// 2l, 2l+1). Scatter: red.global.add.v2.f32 from all 32 lanes.
__global__ __launch_bounds__(128, 5)
void conv_kernel(const float* __restrict__ feats,
                 const float* __restrict__ weight,
                 const void*  __restrict__ in_idx,
                 const void*  __restrict__ out_idx,
                 float*       __restrict__ out) {
    const int k    = blockIdx.y;
    const int lane = threadIdx.x & 31;
    const int warp = threadIdx.x >> 5;

    __shared__ ulonglong2 stage[4][2][32 * 8];   // warp x buffer x (32 rows x 8 chunks)

    const int b0 = (blockIdx.x * 4 + warp) * NB;
    if (b0 >= NBATCH) return;

    // Pack weights from global: wp0[c2] = (W[2c2][2l], W[2c2+1][2l]); wp1 for 2l+1.
    const float* wk = weight + (long long)k * CIN * COUT;
    unsigned long long wp0[16], wp1[16];
#pragma unroll
    for (int c2 = 0; c2 < 16; c2++) {
        wp0[c2] = pack2(__ldg(wk + (2*c2) * COUT + 2*lane),
                        __ldg(wk + (2*c2+1) * COUT + 2*lane));
        wp1[c2] = pack2(__ldg(wk + (2*c2) * COUT + 2*lane + 1),
                        __ldg(wk + (2*c2+1) * COUT + 2*lane + 1));
    }

    const int is64 = g_is64;
    const long long base = (long long)k * NPAIRS;
    const int sub = lane >> 3;          // row-within-group of 4
    const int q   = lane & 7;           // 16B chunk within row
    const unsigned int sb0 = (unsigned int)__cvta_generic_to_shared(&stage[warp][0][0]);
    const unsigned int sb1 = (unsigned int)__cvta_generic_to_shared(&stage[warp][1][0]);

    // index position for batch b (clamped; overflow batches never computed)
    auto idx_pos = [&](int b) -> long long {
        int bc = (b < NBATCH) ? b : NBATCH - 1;
        return base + bc * 32 + lane;
    };

    // issue the 8 cp.asyncs for a batch into buffer sbuf, given its ir
    auto issue = [&](int ir, unsigned int sbuf) {
#pragma unroll
        for (int g = 0; g < 8; g++) {
            const int r    = 4 * g + sub;
            const int irow = __shfl_sync(0xffffffffu, ir, r);
            cp_async16(sbuf + (r * 8 + q) * 16,
                       (const char*)(feats + (long long)irow * CIN) + q * 16);
        }
    };

    // ---- prologue ----
    int cur_ir = load_idx(in_idx,  idx_pos(b0), is64);
    int cur_or = load_idx(out_idx, idx_pos(b0), is64);
    issue(cur_ir, sb0);
    CP_COMMIT();
    int nxt_ir = load_idx(in_idx,  idx_pos(b0 + 1), is64);
    int nxt_or = load_idx(out_idx, idx_pos(b0 + 1), is64);

    unsigned int sbuf_cur = sb0, sbuf_nxt = sb1;
    ulonglong2* st_cur = &stage[warp][0][0];
    ulonglong2* st_nxt = &stage[warp][1][0];

    for (int t = 0; t < NB; t++) {
        const int b = b0 + t;
        if (b >= NBATCH) break;

        // issue loads for batch t+1 (if it exists); always commit to keep
        // wait_group accounting exact
        if (t + 1 < NB && b + 1 < NBATCH) issue(nxt_ir, sbuf_nxt);
        CP_COMMIT();

        // prefetch indices for batch t+2 (consumed next iteration)
        int pf_ir = load_idx(in_idx,  idx_pos(b + 2), is64);
        int pf_or = load_idx(out_idx, idx_pos(b + 2), is64);

        CP_WAIT1();
        __syncwarp();

        // ---- compute batch t: 2 records per iteration ----
        const int orow = cur_or;
        for (int j = 0; j < 32; j += 2) {
            const int ro0 = __shfl_sync(0xffffffffu, orow, j);
            const int ro1 = __shfl_sync(0xffffffffu, orow, j + 1);
            const ulonglong2* r0 = st_cur + j * 8;
            const ulonglong2* r1 = r0 + 8;
            unsigned long long a0 = 0ull, a1 = 0ull, c0 = 0ull, c1 = 0ull;
#pragma unroll
            for (int c = 0; c < 8; c++) {
                ulonglong2 f0 = r0[c];      // broadcast LDS.128
                ulonglong2 f1 = r1[c];
                FMA2(a0, f0.x, wp0[2*c]);   FMA2(a1, f0.x, wp1[2*c]);
                FMA2(c0, f1.x, wp0[2*c]);   FMA2(c1, f1.x, wp1[2*c]);
                FMA2(a0, f0.y, wp0[2*c+1]); FMA2(a1, f0.y, wp1[2*c+1]);
                FMA2(c0, f1.y, wp0[2*c+1]); FMA2(c1, f1.y, wp1[2*c+1]);
            }
            red_add_v2(out + (long long)ro0 * COUT + 2*lane, hadd2(a0), hadd2(a1));
            red_add_v2(out + (long long)ro1 * COUT + 2*lane, hadd2(c0), hadd2(c1));
        }
        __syncwarp();                       // stage reuse safety

        // rotate
        cur_ir = nxt_ir;  cur_or = nxt_or;
        nxt_ir = pf_ir;   nxt_or = pf_or;
        unsigned int ts = sbuf_cur; sbuf_cur = sbuf_nxt; sbuf_nxt = ts;
        ulonglong2* tp = st_cur; st_cur = st_nxt; st_nxt = tp;
    }
}

// GroupNorm stats: 2 float4 rows per thread per iteration (double MLP).
__global__ void stats_kernel(const float4* __restrict__ out) {
    const int c4   = threadIdx.x & 15;
    const int ty   = threadIdx.x >> 4;
    const int lane = threadIdx.x & 31;
    __shared__ float s_sum[NGRP], s_sq[NGRP];
    if (threadIdx.x < NGRP) { s_sum[threadIdx.x] = 0.f; s_sq[threadIdx.x] = 0.f; }
    __syncthreads();

    float sum = 0.f, sq = 0.f;
    for (int row = blockIdx.x * 32 + ty; row < NPTS; row += gridDim.x * 32) {
        float4 v = __ldg(out + row * 16 + c4);
        int row2 = row + 16;
        if (row2 < NPTS) {
            float4 u = __ldg(out + row2 * 16 + c4);
            sum += (u.x + u.y) + (u.z + u.w);
            sq   = fmaf(u.x, u.x, fmaf(u.y, u.y, fmaf(u.z, u.z, fmaf(u.w, u.w, sq))));
        }
        sum += (v.x + v.y) + (v.z + v.w);
        sq   = fmaf(v.x, v.x, fmaf(v.y, v.y, fmaf(v.z, v.z, fmaf(v.w, v.w, sq))));
    }
    // lanes {2g, 2g+1, 2g+16, 2g+17} share group g
    sum += __shfl_xor_sync(0xffffffffu, sum, 16);
    sq  += __shfl_xor_sync(0xffffffffu, sq,  16);
    sum += __shfl_xor_sync(0xffffffffu, sum, 1);
    sq  += __shfl_xor_sync(0xffffffffu, sq,  1);
    if (lane < 16 && !(lane & 1)) {
        atomicAdd(&s_sum[lane >> 1], sum);
        atomicAdd(&s_sq[lane >> 1],  sq);
    }
    __syncthreads();
    if (threadIdx.x < NGRP) {
        atomicAdd(&g_sum[threadIdx.x], s_sum[threadIdx.x]);
        atomicAdd(&g_sq[threadIdx.x],  s_sq[threadIdx.x]);
    }
}

__device__ __forceinline__ float4 aff_lrelu(float4 v, float4 ga, float4 be) {
    v.x = fmaf(v.x, ga.x, be.x); v.x = (v.x >= 0.f) ? v.x : 0.01f * v.x;
    v.y = fmaf(v.y, ga.y, be.y); v.y = (v.y >= 0.f) ? v.y : 0.01f * v.y;
    v.z = fmaf(v.z, ga.z, be.z); v.z = (v.z >= 0.f) ? v.z : 0.01f * v.z;
    v.w = fmaf(v.w, ga.w, be.w); v.w = (v.w >= 0.f) ? v.w : 0.01f * v.w;
    return v;
}

// Fused finalize + affine + LeakyReLU: mean/inv computed inline from the
// global accumulators (kernel boundary after stats_kernel is the sync).
__global__ void norm_kernel(float4* __restrict__ out,
                            const float4* __restrict__ gamma4,
                            const float4* __restrict__ beta4) {
    const int c4 = threadIdx.x & 15;
    const int ty = threadIdx.x >> 4;
    const int g  = c4 >> 1;
    const float cnt = (float)NPTS * (COUT / NGRP);
    const float m   = g_sum[g] / cnt;
    const float var = g_sq[g] / cnt - m * m;
    const float inv = rsqrtf(var + 1e-5f);
    float4 ga = __ldg(gamma4 + c4);
    float4 be = __ldg(beta4  + c4);
    ga.x *= inv; ga.y *= inv; ga.z *= inv; ga.w *= inv;
    be.x -= m * ga.x; be.y -= m * ga.y; be.z -= m * ga.z; be.w -= m * ga.w;
    for (int row = blockIdx.x * 32 + ty; row < NPTS; row += gridDim.x * 32) {
        float4 v = out[row * 16 + c4];
        int row2 = row + 16;
        float4 u;
        bool has2 = (row2 < NPTS);
        if (has2) u = out[row2 * 16 + c4];
        out[row * 16 + c4] = aff_lrelu(v, ga, be);
        if (has2) out[row2 * 16 + c4] = aff_lrelu(u, ga, be);
    }
}

extern "C" void kernel_launch(void* const* d_in, const int* in_sizes, int n_in,
                              void* d_out, int out_size) {
    const float* feats   = (const float*)d_in[0];
    const float* weight  = (const float*)d_in[1];
    const float* gamma   = (const float*)d_in[2];
    const float* beta    = (const float*)d_in[3];
    const void*  in_idx  = d_in[4];
    const void*  out_idx = d_in[5];
    float* out = (float*)d_out;

    const int n4 = NPTS * COUT / 4;
    zero_kernel<<<(n4 + 255) / 256, 256>>>((float4*)out, n4,
                                           (const unsigned int*)in_idx);

    const int warps_per_k  = (NBATCH + NB - 1) / NB;          // 625
    const int blocks_per_k = (warps_per_k + 3) / 4;           // 157
    dim3 cgrid(blocks_per_k, KOFF);
    conv_kernel<<<cgrid, 128>>>(feats, weight, in_idx, out_idx, out);

    stats_kernel<<<1184, 256>>>((const float4*)out);
    norm_kernel<<<1184, 256>>>((float4*)out, (const float4*)gamma, (const float4*)beta);
}